// round 12
// baseline (speedup 1.0000x reference)
#include <cuda_runtime.h>
#include <cuda_fp16.h>
#include <math.h>

#define M_TOT   8192
#define KDIM    512
#define NDIM    512
#define S_LEN   1024
#define NHEADS  8
#define DHEAD   64
#define GBN     64
#define WSZ     262144
#define KW      256        // k-words (half2) per row

// -------- scratch (packed half2 words) --------
__device__ unsigned g_Xh[(size_t)M_TOT * KW];
__device__ unsigned g_Wh[5 * WSZ / 2];              // transposed [w][n][k/2]
__device__ unsigned g_Qh[GBN * S_LEN * 32];         // [gbn][s][d/2]
__device__ unsigned g_Kh[GBN * S_LEN * 32];
__device__ unsigned g_Vh[GBN * DHEAD * 512];        // TRANSPOSED [gbn][d][s/2]
__device__ unsigned g_AGh[(size_t)M_TOT * 256];     // [row][n/2]
__device__ float    g_Gate[(size_t)M_TOT * NDIM];
__device__ float    g_tsin[S_LEN * 32];
__device__ float    g_tcos[S_LEN * 32];
__device__ float    g_tscl[S_LEN * 32];

__device__ __forceinline__ unsigned packh2(float a, float b) {
    __half2 h = __floats2half2_rn(a, b);
    return *reinterpret_cast<unsigned*>(&h);
}
__device__ __forceinline__ void mma_f16(float* c, const unsigned* a, const unsigned* b) {
    asm volatile(
        "mma.sync.aligned.m16n8k16.row.col.f32.f16.f16.f32 "
        "{%0,%1,%2,%3},{%4,%5,%6,%7},{%8,%9},{%0,%1,%2,%3};"
        : "+f"(c[0]), "+f"(c[1]), "+f"(c[2]), "+f"(c[3])
        : "r"(a[0]), "r"(a[1]), "r"(a[2]), "r"(a[3]), "r"(b[0]), "r"(b[1]));
}
__device__ __forceinline__ void ldsm4(unsigned& r0, unsigned& r1,
                                      unsigned& r2, unsigned& r3, unsigned addr) {
    asm volatile("ldmatrix.sync.aligned.m8n8.x4.shared.b16 {%0,%1,%2,%3}, [%4];"
                 : "=r"(r0), "=r"(r1), "=r"(r2), "=r"(r3) : "r"(addr));
}
__device__ __forceinline__ float silu_f(float x) {
    return x / (1.0f + __expf(-x));
}
__device__ __forceinline__ unsigned s2u(const void* p) {
    return (unsigned)__cvta_generic_to_shared(p);
}
#define CPA16(d, s) asm volatile("cp.async.ca.shared.global [%0], [%1], 16;" :: "r"(d), "l"(s))
#define CP_COMMIT() asm volatile("cp.async.commit_group;")
#define CP_WAIT(n)  asm volatile("cp.async.wait_group %0;" :: "n"(n))

// =================================================================
// prep (unchanged, known-good)
// =================================================================
__global__ void prep_k(const float* __restrict__ X, const float* __restrict__ WQ,
                       const float* __restrict__ WK, const float* __restrict__ WV,
                       const float* __restrict__ WG, const float* __restrict__ WO)
{
    int idx = blockIdx.x * 256 + threadIdx.x;
    const int XW = M_TOT * KW;
    if (idx < XW) {
        int row = idx >> 8, kw = idx & 255;
        const float* p = X + (size_t)row * KDIM + 2 * kw;
        g_Xh[idx] = packh2(p[0], p[1]);
        return;
    }
    int off = idx - XW;
    if (off < 5 * (WSZ / 2)) {
        int w = off >> 17, sub = off & (WSZ / 2 - 1);
        int n = sub >> 8, kw = sub & 255;
        int k0 = kw * 2;
        float v0, v1;
        if (w < 3) {
            const float* p = (w == 0) ? WQ : (w == 1) ? WK : WV;
            size_t hb = (size_t)(n >> 6) * (KDIM * DHEAD) + (n & 63);
            v0 = p[hb + (size_t)k0 * DHEAD];
            v1 = p[hb + (size_t)(k0 + 1) * DHEAD];
        } else {
            const float* p = (w == 3) ? WG : WO;
            v0 = p[(size_t)k0 * NDIM + n];
            v1 = p[(size_t)(k0 + 1) * NDIM + n];
        }
        g_Wh[off] = packh2(v0, v1);
        return;
    }
    int t = off - 5 * (WSZ / 2);
    if (t < S_LEN * 32) {
        int s = t >> 5, j = t & 31;
        double invf = pow(10000.0, -(double)j / 32.0);
        double ang = (double)s * invf;
        g_tsin[t] = (float)sin(ang);
        g_tcos[t] = (float)cos(ang);
        double sv = (2.0 * j + 0.4 * 64.0) / (1.4 * 64.0);
        g_tscl[t] = (float)pow(sv, (double)s / 512.0);
    }
}

// =================================================================
// fp16 GEMM (unchanged, known-good)
// =================================================================
#define NIT 16

template<int MODE, int BN>
__global__ void __launch_bounds__(256) gemm_h(float* __restrict__ Cout)
{
    constexpr int NT = BN / 32;
    extern __shared__ unsigned gsm[];
    unsigned (*As)[20] = (unsigned(*)[20])gsm;
    unsigned (*Bs)[20] = (unsigned(*)[20])(gsm + 3 * 128 * 20);
    const unsigned AsU = s2u(As), BsU = s2u(Bs);

    const int bz = (MODE == 0) ? blockIdx.z : 4;
    const unsigned* Ag = (MODE == 0) ? g_Xh : g_AGh;
    const unsigned* Bg = g_Wh + (size_t)bz * (WSZ / 2);

    const int bm = blockIdx.y * 128;
    const int bn = blockIdx.x * BN;
    const int tid = threadIdx.x;
    const int warp = tid >> 5, lane = tid & 31;
    const int grp = lane >> 2, tig = lane & 3;
    const int wm = (warp & 3) * 32, wn = (warp >> 2) * (BN / 2);

    const int aRow = (lane & 7) + ((lane >> 3) & 1) * 8;
    const int aKof = ((lane >> 4) & 1) * 4;
    const int bRow = (lane & 7) + ((lane >> 4) & 1) * 8;
    const int bKof = ((lane >> 3) & 1) * 4;

    float acc[2][NT * 2][4];
#pragma unroll
    for (int mt = 0; mt < 2; mt++)
#pragma unroll
        for (int nt = 0; nt < NT * 2; nt++)
#pragma unroll
            for (int i = 0; i < 4; i++) acc[mt][nt][i] = 0.0f;

    auto load_stage = [&](int s) {
        const int st = s % 3;
#pragma unroll
        for (int r = 0; r < 2; r++) {
            int c = tid + r * 256;
            int row = c >> 2, w4 = (c & 3) * 4;
            CPA16(s2u(&As[st * 128 + row][w4]),
                  &Ag[(size_t)(bm + row) * KW + s * 16 + w4]);
        }
#pragma unroll
        for (int r = 0; r < (BN == 128 ? 2 : 1); r++) {
            int c = tid + r * 256;
            int row = c >> 2, w4 = (c & 3) * 4;
            CPA16(s2u(&Bs[st * BN + row][w4]),
                  &Bg[(size_t)(bn + row) * KW + s * 16 + w4]);
        }
    };

    load_stage(0); CP_COMMIT();
    load_stage(1); CP_COMMIT();

    for (int it = 0; it < NIT; it++) {
        const int st = it % 3;
        if (it + 1 < NIT) { CP_WAIT(1); } else { CP_WAIT(0); }
        __syncthreads();
        if (it + 2 < NIT) { load_stage(it + 2); CP_COMMIT(); }

#pragma unroll
        for (int ks = 0; ks < 2; ks++) {
            int kw = ks * 8;
            unsigned aF[2][4];
#pragma unroll
            for (int mt = 0; mt < 2; mt++) {
                unsigned addr = AsU +
                    (((st * 128 + wm + mt * 16 + aRow) * 20) + kw + aKof) * 4;
                ldsm4(aF[mt][0], aF[mt][1], aF[mt][2], aF[mt][3], addr);
            }
#pragma unroll
            for (int p = 0; p < NT; p++) {
                unsigned b[4];
                unsigned addr = BsU +
                    (((st * BN + wn + p * 16 + bRow) * 20) + kw + bKof) * 4;
                ldsm4(b[0], b[1], b[2], b[3], addr);
                mma_f16(acc[0][2 * p],     aF[0], b);
                mma_f16(acc[1][2 * p],     aF[1], b);
                mma_f16(acc[0][2 * p + 1], aF[0], b + 2);
                mma_f16(acc[1][2 * p + 1], aF[1], b + 2);
            }
        }
    }

#pragma unroll
    for (int mt = 0; mt < 2; mt++) {
        int row0 = bm + wm + mt * 16 + grp;
#pragma unroll
        for (int nt = 0; nt < NT * 2; nt++) {
            int col = bn + wn + nt * 8 + tig * 2;
#pragma unroll
            for (int h = 0; h < 2; h++) {
                int row = row0 + h * 8;
                float c0 = acc[mt][nt][h * 2], c1 = acc[mt][nt][h * 2 + 1];
                if (MODE == 0) {
                    if (bz == 3) {
                        *(float2*)&g_Gate[(size_t)row * NDIM + col] =
                            make_float2(silu_f(c0), silu_f(c1));
                    } else {
                        int gH = col >> 6, d = col & 63;
                        int s = row & (S_LEN - 1), bnI = row >> 10;
                        float o0 = c0, o1 = c1;
                        if (bz < 2) {
                            int ti = (s << 5) + (d >> 1);
                            float sn = g_tsin[ti], cs = g_tcos[ti], sc = g_tscl[ti];
                            if (bz == 1) sc = 1.0f / sc;
                            o0 = (c0 * cs - c1 * sn) * sc;
                            o1 = (c1 * cs + c0 * sn) * sc;
                        }
                        int gb = gH * 8 + bnI;
                        if (bz == 2) {
                            __half* vp = (__half*)g_Vh;
                            vp[((size_t)gb * 64 + d) * S_LEN + s]     = __float2half_rn(o0);
                            vp[((size_t)gb * 64 + d + 1) * S_LEN + s] = __float2half_rn(o1);
                        } else {
                            unsigned* dst = (bz == 0) ? g_Qh : g_Kh;
                            dst[((size_t)gb * S_LEN + s) * 32 + (d >> 1)] = packh2(o0, o1);
                        }
                    }
                } else {
                    *(float2*)&Cout[(size_t)row * NDIM + col] = make_float2(c0, c1);
                }
            }
        }
    }
}
#define GEMM_SMEM0 ((3 * 128 * 20 + 3 * 128 * 20) * 4)
#define GEMM_SMEM2 ((3 * 128 * 20 + 3 * 64 * 20) * 4)

// =================================================================
// Retention fp16: 32-row warp tiles (Q tile 256/CTA), register S,
// hoisted Q fragments, ldmatrix K/V. 256 thr, K/V tile 64, 3-stage
// cp.async. Stride 36 words. Fused GroupNorm + gate.
// =================================================================
#define ATTN_SMEM ((256 * 36 + 192 * 36 + 192 * 36) * 4)

__global__ void __launch_bounds__(256) attn_h(const float* __restrict__ gnw,
                                              const float* __restrict__ gnb)
{
    extern __shared__ unsigned sm4[];
    unsigned (*Qs)[36]  = (unsigned(*)[36])sm4;                 // 256 x [d/2]
    unsigned (*Ks)[36]  = (unsigned(*)[36])(sm4 + 256 * 36);    // 3*64 x [d/2]
    unsigned (*VsT)[36] = (unsigned(*)[36])(sm4 + 448 * 36);    // 3*64 (d) x [key/2]
    const unsigned QsU = s2u(Qs), KsU = s2u(Ks), VsU = s2u(VsT);

    const int qt  = 3 - blockIdx.x;      // big blocks first
    const int gbn = blockIdx.y;
    const int g  = gbn >> 3;
    const int bn = gbn & 7;
    const int qbase = qt * 256;

    const unsigned* Qp = g_Qh + (size_t)gbn * S_LEN * 32;
    const unsigned* Kp = g_Kh + (size_t)gbn * S_LEN * 32;
    const unsigned* Vp = g_Vh + (size_t)gbn * DHEAD * 512;

    const int tid = threadIdx.x;
    const int warp = tid >> 5, lane = tid & 31;
    const int grp = lane >> 2, tig = lane & 3;

    const int aRow = (lane & 7) + ((lane >> 3) & 1) * 8;
    const int aKof = ((lane >> 4) & 1) * 4;
    const int bRow = (lane & 7) + ((lane >> 4) & 1) * 8;
    const int bKof = ((lane >> 3) & 1) * 4;

    double tt = log(1.0 / 32.0) + (double)g * (log(1.0 / 512.0) - log(1.0 / 32.0)) / 7.0;
    const float lng = (float)log(1.0 - exp(tt));

    auto load_kv = [&](int kt, int st) {
        int kbase = kt * 64;
#pragma unroll
        for (int r = 0; r < 2; r++) {
            int c = tid + r * 256;
            int row = c >> 3, w4 = (c & 7) * 4;
            CPA16(s2u(&Ks[st * 64 + row][w4]), &Kp[(size_t)(kbase + row) * 32 + w4]);
        }
#pragma unroll
        for (int r = 0; r < 2; r++) {
            int c = tid + r * 256;
            int row = c >> 3, w4 = (c & 7) * 4;   // row = d
            CPA16(s2u(&VsT[st * 64 + row][w4]), &Vp[(size_t)row * 512 + (kbase >> 1) + w4]);
        }
    };

    const int nkt = 4 * qt + 4;

    // Q tile (256 rows x 32 words): 8 chunk-iters
#pragma unroll
    for (int r = 0; r < 8; r++) {
        int c = tid + r * 256;
        int row = c >> 3, w4 = (c & 7) * 4;
        CPA16(s2u(&Qs[row][w4]), &Qp[(size_t)(qbase + row) * 32 + w4]);
    }
    load_kv(0, 0); CP_COMMIT();
    load_kv(1, 1); CP_COMMIT();

    // decay coefficients (registers, loop-invariant)
    const int rq = warp * 32;
    float eq[2][2], cej0[8], cej1[8];
#pragma unroll
    for (int mt = 0; mt < 2; mt++) {
        eq[mt][0] = __expf(lng * (float)(rq + mt * 16 + grp));
        eq[mt][1] = __expf(lng * (float)(rq + mt * 16 + grp + 8));
    }
#pragma unroll
    for (int nt = 0; nt < 8; nt++) {
        int jl = nt * 8 + tig * 2;
        cej0[nt] = __expf(lng * (float)(63 - jl));
        cej1[nt] = __expf(lng * (float)(62 - jl));
    }

    float yacc[2][8][4];
#pragma unroll
    for (int mt = 0; mt < 2; mt++)
#pragma unroll
        for (int nt = 0; nt < 8; nt++)
#pragma unroll
            for (int i = 0; i < 4; i++) yacc[mt][nt][i] = 0.0f;

    unsigned qF[2][4][4];

    for (int kt = 0; kt < nkt; kt++) {
        const int st = kt % 3;
        const int kbase = kt * 64;
        if (kt + 1 < nkt) { CP_WAIT(1); } else { CP_WAIT(0); }
        __syncthreads();
        if (kt + 2 < nkt) { load_kv(kt + 2, (kt + 2) % 3); CP_COMMIT(); }

        if (kt == 0) {
#pragma unroll
            for (int mt = 0; mt < 2; mt++)
#pragma unroll
                for (int ks = 0; ks < 4; ks++) {
                    unsigned addr = QsU +
                        (((rq + mt * 16 + aRow) * 36) + ks * 8 + aKof) * 4;
                    ldsm4(qF[mt][ks][0], qF[mt][ks][1],
                          qF[mt][ks][2], qF[mt][ks][3], addr);
                }
        }

        // ---- mma1: scores = Q @ K^T ----
        float sacc[2][8][4];
#pragma unroll
        for (int mt = 0; mt < 2; mt++)
#pragma unroll
            for (int nt = 0; nt < 8; nt++)
#pragma unroll
                for (int i = 0; i < 4; i++) sacc[mt][nt][i] = 0.0f;

#pragma unroll
        for (int ks = 0; ks < 4; ks++) {
#pragma unroll
            for (int p = 0; p < 4; p++) {
                unsigned b[4];
                unsigned addr = KsU + (((st * 64 + p * 16 + bRow) * 36) + ks * 8 + bKof) * 4;
                ldsm4(b[0], b[1], b[2], b[3], addr);
                mma_f16(sacc[0][2 * p],     qF[0][ks], b);
                mma_f16(sacc[0][2 * p + 1], qF[0][ks], b + 2);
                mma_f16(sacc[1][2 * p],     qF[1][ks], b);
                mma_f16(sacc[1][2 * p + 1], qF[1][ks], b + 2);
            }
        }

        // ---- decay + mask in place ----
        const float tf = __expf(lng * (float)(qbase - kbase - 63));
        const bool edge = (kt >= nkt - 4);
#pragma unroll
        for (int mt = 0; mt < 2; mt++) {
            const float d0 = eq[mt][0] * tf, d1 = eq[mt][1] * tf;
#pragma unroll
            for (int nt = 0; nt < 8; nt++) {
                sacc[mt][nt][0] *= d0 * cej0[nt];
                sacc[mt][nt][1] *= d0 * cej1[nt];
                sacc[mt][nt][2] *= d1 * cej0[nt];
                sacc[mt][nt][3] *= d1 * cej1[nt];
                if (edge) {
                    int kj = kbase + nt * 8 + tig * 2;
                    int qi0 = qbase + rq + mt * 16 + grp, qi1 = qi0 + 8;
                    if (qi0 < kj)     sacc[mt][nt][0] = 0.0f;
                    if (qi0 < kj + 1) sacc[mt][nt][1] = 0.0f;
                    if (qi1 < kj)     sacc[mt][nt][2] = 0.0f;
                    if (qi1 < kj + 1) sacc[mt][nt][3] = 0.0f;
                }
            }
        }

        // ---- mma2: Y += S @ V^T-tile (pack aS per k2, shared V frags) ----
#pragma unroll
        for (int k2 = 0; k2 < 4; k2++) {
            unsigned aS0[4], aS1[4];
            aS0[0] = packh2(sacc[0][2 * k2][0],     sacc[0][2 * k2][1]);
            aS0[1] = packh2(sacc[0][2 * k2][2],     sacc[0][2 * k2][3]);
            aS0[2] = packh2(sacc[0][2 * k2 + 1][0], sacc[0][2 * k2 + 1][1]);
            aS0[3] = packh2(sacc[0][2 * k2 + 1][2], sacc[0][2 * k2 + 1][3]);
            aS1[0] = packh2(sacc[1][2 * k2][0],     sacc[1][2 * k2][1]);
            aS1[1] = packh2(sacc[1][2 * k2][2],     sacc[1][2 * k2][3]);
            aS1[2] = packh2(sacc[1][2 * k2 + 1][0], sacc[1][2 * k2 + 1][1]);
            aS1[3] = packh2(sacc[1][2 * k2 + 1][2], sacc[1][2 * k2 + 1][3]);
#pragma unroll
            for (int p = 0; p < 4; p++) {
                unsigned b[4];
                unsigned addr = VsU + (((st * 64 + p * 16 + bRow) * 36) + k2 * 8 + bKof) * 4;
                ldsm4(b[0], b[1], b[2], b[3], addr);
                mma_f16(yacc[0][2 * p],     aS0, b);
                mma_f16(yacc[0][2 * p + 1], aS0, b + 2);
                mma_f16(yacc[1][2 * p],     aS1, b);
                mma_f16(yacc[1][2 * p + 1], aS1, b + 2);
            }
        }
    }

    // ---- GroupNorm + gate + half2 store ----
#pragma unroll
    for (int mt = 0; mt < 2; mt++) {
#pragma unroll
        for (int h = 0; h < 2; h++) {
            int rl = rq + mt * 16 + grp + h * 8;
            int qi = qbase + rl;
            float s = 0.0f, sq = 0.0f;
#pragma unroll
            for (int nt = 0; nt < 8; nt++) {
                float v0 = yacc[mt][nt][h * 2], v1 = yacc[mt][nt][h * 2 + 1];
                s += v0 + v1;
                sq += v0 * v0 + v1 * v1;
            }
            s  += __shfl_xor_sync(0xffffffffu, s, 1);
            s  += __shfl_xor_sync(0xffffffffu, s, 2);
            sq += __shfl_xor_sync(0xffffffffu, sq, 1);
            sq += __shfl_xor_sync(0xffffffffu, sq, 2);
            float mean = s * (1.0f / 64.0f);
            float var = sq * (1.0f / 64.0f) - mean * mean;
            float rstd = rsqrtf(var + 1e-5f);
            size_t fbase = ((size_t)bn * S_LEN + qi) * NDIM + g * 64;
#pragma unroll
            for (int nt = 0; nt < 8; nt++) {
                int col = nt * 8 + tig * 2;
                float w0 = gnw[g * 64 + col], w1 = gnw[g * 64 + col + 1];
                float b0 = gnb[g * 64 + col], b1 = gnb[g * 64 + col + 1];
                float2 gt = *(const float2*)&g_Gate[fbase + col];
                float o0 = ((yacc[mt][nt][h * 2]     - mean) * rstd * w0 + b0) * gt.x;
                float o1 = ((yacc[mt][nt][h * 2 + 1] - mean) * rstd * w1 + b1) * gt.y;
                g_AGh[(fbase + col) >> 1] = packh2(o0, o1);
            }
        }
    }
}

// =================================================================
extern "C" void kernel_launch(void* const* d_in, const int* in_sizes, int n_in,
                              void* d_out, int out_size)
{
    const float* X   = (const float*)d_in[0];
    const float* WQ  = (const float*)d_in[1];
    const float* WK  = (const float*)d_in[2];
    const float* WV  = (const float*)d_in[3];
    const float* WG  = (const float*)d_in[4];
    const float* WO  = (const float*)d_in[5];
    const float* gnw = (const float*)d_in[6];
    const float* gnb = (const float*)d_in[7];
    float* out = (float*)d_out;

    cudaFuncSetAttribute((const void*)gemm_h<0, 128>,
                         cudaFuncAttributeMaxDynamicSharedMemorySize, GEMM_SMEM0);
    cudaFuncSetAttribute((const void*)gemm_h<2, 64>,
                         cudaFuncAttributeMaxDynamicSharedMemorySize, GEMM_SMEM2);
    cudaFuncSetAttribute((const void*)attn_h,
                         cudaFuncAttributeMaxDynamicSharedMemorySize, ATTN_SMEM);

    int prep_elems = M_TOT * KW + 5 * (WSZ / 2) + S_LEN * 32;
    prep_k<<<(prep_elems + 255) / 256, 256>>>(X, WQ, WK, WV, WG, WO);

    gemm_h<0, 128><<<dim3(NDIM / 128, M_TOT / 128, 4), 256, GEMM_SMEM0>>>(nullptr);
    attn_h<<<dim3(4, GBN), 256, ATTN_SMEM>>>(gnw, gnb);
    gemm_h<2, 64><<<dim3(NDIM / 64, M_TOT / 128, 1), 256, GEMM_SMEM2>>>(out);
}

// round 13
// speedup vs baseline: 1.0312x; 1.0312x over previous
#include <cuda_runtime.h>
#include <cuda_fp16.h>
#include <math.h>

#define M_TOT   8192
#define KDIM    512
#define NDIM    512
#define S_LEN   1024
#define NHEADS  8
#define DHEAD   64
#define GBN     64
#define WSZ     262144
#define KW      256        // k-words (half2) per row

// -------- scratch (packed half2 words) --------
__device__ unsigned g_Xh[(size_t)M_TOT * KW];
__device__ unsigned g_Wh[5 * WSZ / 2];              // transposed [w][n][k/2]
__device__ unsigned g_Qh[GBN * S_LEN * 32];         // [gbn][s][d/2]
__device__ unsigned g_Kh[GBN * S_LEN * 32];
__device__ unsigned g_Vh[GBN * DHEAD * 512];        // TRANSPOSED [gbn][d][s/2]
__device__ unsigned g_AGh[(size_t)M_TOT * 256];     // [row][n/2]
__device__ float    g_Gate[(size_t)M_TOT * NDIM];
__device__ float    g_tsin[S_LEN * 32];
__device__ float    g_tcos[S_LEN * 32];
__device__ float    g_tscl[S_LEN * 32];

__device__ __forceinline__ unsigned packh2(float a, float b) {
    __half2 h = __floats2half2_rn(a, b);
    return *reinterpret_cast<unsigned*>(&h);
}
__device__ __forceinline__ void mma_f16(float* c, const unsigned* a, const unsigned* b) {
    asm volatile(
        "mma.sync.aligned.m16n8k16.row.col.f32.f16.f16.f32 "
        "{%0,%1,%2,%3},{%4,%5,%6,%7},{%8,%9},{%0,%1,%2,%3};"
        : "+f"(c[0]), "+f"(c[1]), "+f"(c[2]), "+f"(c[3])
        : "r"(a[0]), "r"(a[1]), "r"(a[2]), "r"(a[3]), "r"(b[0]), "r"(b[1]));
}
__device__ __forceinline__ void ldsm4(unsigned& r0, unsigned& r1,
                                      unsigned& r2, unsigned& r3, unsigned addr) {
    asm volatile("ldmatrix.sync.aligned.m8n8.x4.shared.b16 {%0,%1,%2,%3}, [%4];"
                 : "=r"(r0), "=r"(r1), "=r"(r2), "=r"(r3) : "r"(addr));
}
__device__ __forceinline__ float silu_f(float x) {
    return x / (1.0f + __expf(-x));
}
__device__ __forceinline__ unsigned s2u(const void* p) {
    return (unsigned)__cvta_generic_to_shared(p);
}
#define CPA16(d, s) asm volatile("cp.async.ca.shared.global [%0], [%1], 16;" :: "r"(d), "l"(s))
#define CP_COMMIT() asm volatile("cp.async.commit_group;")
#define CP_WAIT(n)  asm volatile("cp.async.wait_group %0;" :: "n"(n))

// =================================================================
// prep (unchanged, known-good)
// =================================================================
__global__ void prep_k(const float* __restrict__ X, const float* __restrict__ WQ,
                       const float* __restrict__ WK, const float* __restrict__ WV,
                       const float* __restrict__ WG, const float* __restrict__ WO)
{
    int idx = blockIdx.x * 256 + threadIdx.x;
    const int XW = M_TOT * KW;
    if (idx < XW) {
        int row = idx >> 8, kw = idx & 255;
        const float* p = X + (size_t)row * KDIM + 2 * kw;
        g_Xh[idx] = packh2(p[0], p[1]);
        return;
    }
    int off = idx - XW;
    if (off < 5 * (WSZ / 2)) {
        int w = off >> 17, sub = off & (WSZ / 2 - 1);
        int n = sub >> 8, kw = sub & 255;
        int k0 = kw * 2;
        float v0, v1;
        if (w < 3) {
            const float* p = (w == 0) ? WQ : (w == 1) ? WK : WV;
            size_t hb = (size_t)(n >> 6) * (KDIM * DHEAD) + (n & 63);
            v0 = p[hb + (size_t)k0 * DHEAD];
            v1 = p[hb + (size_t)(k0 + 1) * DHEAD];
        } else {
            const float* p = (w == 3) ? WG : WO;
            v0 = p[(size_t)k0 * NDIM + n];
            v1 = p[(size_t)(k0 + 1) * NDIM + n];
        }
        g_Wh[off] = packh2(v0, v1);
        return;
    }
    int t = off - 5 * (WSZ / 2);
    if (t < S_LEN * 32) {
        int s = t >> 5, j = t & 31;
        double invf = pow(10000.0, -(double)j / 32.0);
        double ang = (double)s * invf;
        g_tsin[t] = (float)sin(ang);
        g_tcos[t] = (float)cos(ang);
        double sv = (2.0 * j + 0.4 * 64.0) / (1.4 * 64.0);
        g_tscl[t] = (float)pow(sv, (double)s / 512.0);
    }
}

// =================================================================
// fp16 GEMM (unchanged, known-good)
// =================================================================
#define NIT 16

template<int MODE, int BN>
__global__ void __launch_bounds__(256) gemm_h(float* __restrict__ Cout)
{
    constexpr int NT = BN / 32;
    extern __shared__ unsigned gsm[];
    unsigned (*As)[20] = (unsigned(*)[20])gsm;
    unsigned (*Bs)[20] = (unsigned(*)[20])(gsm + 3 * 128 * 20);
    const unsigned AsU = s2u(As), BsU = s2u(Bs);

    const int bz = (MODE == 0) ? blockIdx.z : 4;
    const unsigned* Ag = (MODE == 0) ? g_Xh : g_AGh;
    const unsigned* Bg = g_Wh + (size_t)bz * (WSZ / 2);

    const int bm = blockIdx.y * 128;
    const int bn = blockIdx.x * BN;
    const int tid = threadIdx.x;
    const int warp = tid >> 5, lane = tid & 31;
    const int grp = lane >> 2, tig = lane & 3;
    const int wm = (warp & 3) * 32, wn = (warp >> 2) * (BN / 2);

    const int aRow = (lane & 7) + ((lane >> 3) & 1) * 8;
    const int aKof = ((lane >> 4) & 1) * 4;
    const int bRow = (lane & 7) + ((lane >> 4) & 1) * 8;
    const int bKof = ((lane >> 3) & 1) * 4;

    float acc[2][NT * 2][4];
#pragma unroll
    for (int mt = 0; mt < 2; mt++)
#pragma unroll
        for (int nt = 0; nt < NT * 2; nt++)
#pragma unroll
            for (int i = 0; i < 4; i++) acc[mt][nt][i] = 0.0f;

    auto load_stage = [&](int s) {
        const int st = s % 3;
#pragma unroll
        for (int r = 0; r < 2; r++) {
            int c = tid + r * 256;
            int row = c >> 2, w4 = (c & 3) * 4;
            CPA16(s2u(&As[st * 128 + row][w4]),
                  &Ag[(size_t)(bm + row) * KW + s * 16 + w4]);
        }
#pragma unroll
        for (int r = 0; r < (BN == 128 ? 2 : 1); r++) {
            int c = tid + r * 256;
            int row = c >> 2, w4 = (c & 3) * 4;
            CPA16(s2u(&Bs[st * BN + row][w4]),
                  &Bg[(size_t)(bn + row) * KW + s * 16 + w4]);
        }
    };

    load_stage(0); CP_COMMIT();
    load_stage(1); CP_COMMIT();

    for (int it = 0; it < NIT; it++) {
        const int st = it % 3;
        if (it + 1 < NIT) { CP_WAIT(1); } else { CP_WAIT(0); }
        __syncthreads();
        if (it + 2 < NIT) { load_stage(it + 2); CP_COMMIT(); }

#pragma unroll
        for (int ks = 0; ks < 2; ks++) {
            int kw = ks * 8;
            unsigned aF[2][4];
#pragma unroll
            for (int mt = 0; mt < 2; mt++) {
                unsigned addr = AsU +
                    (((st * 128 + wm + mt * 16 + aRow) * 20) + kw + aKof) * 4;
                ldsm4(aF[mt][0], aF[mt][1], aF[mt][2], aF[mt][3], addr);
            }
#pragma unroll
            for (int p = 0; p < NT; p++) {
                unsigned b[4];
                unsigned addr = BsU +
                    (((st * BN + wn + p * 16 + bRow) * 20) + kw + bKof) * 4;
                ldsm4(b[0], b[1], b[2], b[3], addr);
                mma_f16(acc[0][2 * p],     aF[0], b);
                mma_f16(acc[1][2 * p],     aF[1], b);
                mma_f16(acc[0][2 * p + 1], aF[0], b + 2);
                mma_f16(acc[1][2 * p + 1], aF[1], b + 2);
            }
        }
    }

#pragma unroll
    for (int mt = 0; mt < 2; mt++) {
        int row0 = bm + wm + mt * 16 + grp;
#pragma unroll
        for (int nt = 0; nt < NT * 2; nt++) {
            int col = bn + wn + nt * 8 + tig * 2;
#pragma unroll
            for (int h = 0; h < 2; h++) {
                int row = row0 + h * 8;
                float c0 = acc[mt][nt][h * 2], c1 = acc[mt][nt][h * 2 + 1];
                if (MODE == 0) {
                    if (bz == 3) {
                        *(float2*)&g_Gate[(size_t)row * NDIM + col] =
                            make_float2(silu_f(c0), silu_f(c1));
                    } else {
                        int gH = col >> 6, d = col & 63;
                        int s = row & (S_LEN - 1), bnI = row >> 10;
                        float o0 = c0, o1 = c1;
                        if (bz < 2) {
                            int ti = (s << 5) + (d >> 1);
                            float sn = g_tsin[ti], cs = g_tcos[ti], sc = g_tscl[ti];
                            if (bz == 1) sc = 1.0f / sc;
                            o0 = (c0 * cs - c1 * sn) * sc;
                            o1 = (c1 * cs + c0 * sn) * sc;
                        }
                        int gb = gH * 8 + bnI;
                        if (bz == 2) {
                            __half* vp = (__half*)g_Vh;
                            vp[((size_t)gb * 64 + d) * S_LEN + s]     = __float2half_rn(o0);
                            vp[((size_t)gb * 64 + d + 1) * S_LEN + s] = __float2half_rn(o1);
                        } else {
                            unsigned* dst = (bz == 0) ? g_Qh : g_Kh;
                            dst[((size_t)gb * S_LEN + s) * 32 + (d >> 1)] = packh2(o0, o1);
                        }
                    }
                } else {
                    *(float2*)&Cout[(size_t)row * NDIM + col] = make_float2(c0, c1);
                }
            }
        }
    }
}
#define GEMM_SMEM0 ((3 * 128 * 20 + 3 * 128 * 20) * 4)
#define GEMM_SMEM2 ((3 * 128 * 20 + 3 * 64 * 20) * 4)

// =================================================================
// Retention fp16 (R10 structure): 16-row warp tiles, Q tile 128,
// register S (in-place decay), ldmatrix, 3-stage cp.async.
// NEW: __launch_bounds__(256,2) (2 CTAs/SM) + decay-dead tile skip.
// =================================================================
#define ATTN_SMEM (512 * 36 * 4)

__global__ void __launch_bounds__(256, 2) attn_h(const float* __restrict__ gnw,
                                                 const float* __restrict__ gnb)
{
    extern __shared__ unsigned sm4[];
    unsigned (*Qs)[36]  = (unsigned(*)[36])sm4;                 // 128 x [d/2]
    unsigned (*Ks)[36]  = (unsigned(*)[36])(sm4 + 128 * 36);    // 3*64 x [d/2]
    unsigned (*VsT)[36] = (unsigned(*)[36])(sm4 + 320 * 36);    // 3*64 (d) x [key/2]
    const unsigned QsU = s2u(Qs), KsU = s2u(Ks), VsU = s2u(VsT);

    const int qt  = 7 - blockIdx.x;      // big blocks first
    const int gbn = blockIdx.y;
    const int g  = gbn >> 3;
    const int bn = gbn & 7;
    const int qbase = qt * 128;

    const unsigned* Qp = g_Qh + (size_t)gbn * S_LEN * 32;
    const unsigned* Kp = g_Kh + (size_t)gbn * S_LEN * 32;
    const unsigned* Vp = g_Vh + (size_t)gbn * DHEAD * 512;

    const int tid = threadIdx.x;
    const int warp = tid >> 5, lane = tid & 31;
    const int grp = lane >> 2, tig = lane & 3;

    const int aRow = (lane & 7) + ((lane >> 3) & 1) * 8;
    const int aKof = ((lane >> 4) & 1) * 4;
    const int bRow = (lane & 7) + ((lane >> 4) & 1) * 8;
    const int bKof = ((lane >> 3) & 1) * 4;

    double tt = log(1.0 / 32.0) + (double)g * (log(1.0 / 512.0) - log(1.0 / 32.0)) / 7.0;
    const float lng = (float)log(1.0 - exp(tt));

    // decay-dead tile cutoff: contributions < ~3e-6 rel are skipped
    const float dist = -12.8f / lng;      // lng < 0
    int kt0 = 0;
    if (dist < (float)qbase) kt0 = (qbase - (int)dist) >> 6;
    if (kt0 < 0) kt0 = 0;

    auto load_kv = [&](int kt, int st) {
        int kbase = kt * 64;
#pragma unroll
        for (int r = 0; r < 2; r++) {
            int c = tid + r * 256;
            int row = c >> 3, w4 = (c & 7) * 4;
            CPA16(s2u(&Ks[st * 64 + row][w4]), &Kp[(size_t)(kbase + row) * 32 + w4]);
        }
#pragma unroll
        for (int r = 0; r < 2; r++) {
            int c = tid + r * 256;
            int row = c >> 3, w4 = (c & 7) * 4;   // row = d
            CPA16(s2u(&VsT[st * 64 + row][w4]), &Vp[(size_t)row * 512 + (kbase >> 1) + w4]);
        }
    };

    const int nkt = 2 * qt + 2;

#pragma unroll
    for (int r = 0; r < 4; r++) {
        int c = tid + r * 256;
        int row = c >> 3, w4 = (c & 7) * 4;
        CPA16(s2u(&Qs[row][w4]), &Qp[(size_t)(qbase + row) * 32 + w4]);
    }
    load_kv(kt0, kt0 % 3);           CP_COMMIT();
    load_kv(kt0 + 1, (kt0 + 1) % 3); CP_COMMIT();

    // decay coefficients (registers, loop-invariant)
    float eq[2], cej0[8], cej1[8];
    eq[0] = __expf(lng * (float)(warp * 16 + grp));
    eq[1] = __expf(lng * (float)(warp * 16 + grp + 8));
#pragma unroll
    for (int nt = 0; nt < 8; nt++) {
        int jl = nt * 8 + tig * 2;
        cej0[nt] = __expf(lng * (float)(63 - jl));
        cej1[nt] = __expf(lng * (float)(62 - jl));
    }

    float yacc[8][4];
#pragma unroll
    for (int nt = 0; nt < 8; nt++)
#pragma unroll
        for (int i = 0; i < 4; i++) yacc[nt][i] = 0.0f;

    unsigned qF[4][4];
    const int rq = warp * 16;

    for (int kt = kt0; kt < nkt; kt++) {
        const int st = kt % 3;
        const int kbase = kt * 64;
        if (kt + 1 < nkt) { CP_WAIT(1); } else { CP_WAIT(0); }
        __syncthreads();
        if (kt + 2 < nkt) { load_kv(kt + 2, (kt + 2) % 3); CP_COMMIT(); }

        if (kt == kt0) {
#pragma unroll
            for (int ks = 0; ks < 4; ks++) {
                unsigned addr = QsU + (((rq + aRow) * 36) + ks * 8 + aKof) * 4;
                ldsm4(qF[ks][0], qF[ks][1], qF[ks][2], qF[ks][3], addr);
            }
        }

        // ---- mma1: scores = Q @ K^T ----
        float sacc[8][4];
#pragma unroll
        for (int nt = 0; nt < 8; nt++)
#pragma unroll
            for (int i = 0; i < 4; i++) sacc[nt][i] = 0.0f;

#pragma unroll
        for (int ks = 0; ks < 4; ks++) {
#pragma unroll
            for (int p = 0; p < 4; p++) {
                unsigned b[4];
                unsigned addr = KsU + (((st * 64 + p * 16 + bRow) * 36) + ks * 8 + bKof) * 4;
                ldsm4(b[0], b[1], b[2], b[3], addr);
                mma_f16(sacc[2 * p],     qF[ks], b);
                mma_f16(sacc[2 * p + 1], qF[ks], b + 2);
            }
        }

        // ---- decay + mask in place ----
        const float tf = __expf(lng * (float)(qbase - kbase - 63));
        const float d0 = eq[0] * tf, d1 = eq[1] * tf;
        const bool edge = (kt >= nkt - 2);
#pragma unroll
        for (int nt = 0; nt < 8; nt++) {
            sacc[nt][0] *= d0 * cej0[nt];
            sacc[nt][1] *= d0 * cej1[nt];
            sacc[nt][2] *= d1 * cej0[nt];
            sacc[nt][3] *= d1 * cej1[nt];
            if (edge) {
                int kj = kbase + nt * 8 + tig * 2;
                int qi0 = qbase + rq + grp, qi1 = qi0 + 8;
                if (qi0 < kj)     sacc[nt][0] = 0.0f;
                if (qi0 < kj + 1) sacc[nt][1] = 0.0f;
                if (qi1 < kj)     sacc[nt][2] = 0.0f;
                if (qi1 < kj + 1) sacc[nt][3] = 0.0f;
            }
        }

        // ---- mma2: Y += S @ V^T-tile (pack aS per k2) ----
#pragma unroll
        for (int k2 = 0; k2 < 4; k2++) {
            unsigned aS[4];
            aS[0] = packh2(sacc[2 * k2][0],     sacc[2 * k2][1]);
            aS[1] = packh2(sacc[2 * k2][2],     sacc[2 * k2][3]);
            aS[2] = packh2(sacc[2 * k2 + 1][0], sacc[2 * k2 + 1][1]);
            aS[3] = packh2(sacc[2 * k2 + 1][2], sacc[2 * k2 + 1][3]);
#pragma unroll
            for (int p = 0; p < 4; p++) {
                unsigned b[4];
                unsigned addr = VsU + (((st * 64 + p * 16 + bRow) * 36) + k2 * 8 + bKof) * 4;
                ldsm4(b[0], b[1], b[2], b[3], addr);
                mma_f16(yacc[2 * p],     aS, b);
                mma_f16(yacc[2 * p + 1], aS, b + 2);
            }
        }
    }

    // ---- GroupNorm + gate + half2 store ----
#pragma unroll
    for (int h = 0; h < 2; h++) {
        int rl = rq + grp + h * 8;
        int qi = qbase + rl;
        float s = 0.0f, sq = 0.0f;
#pragma unroll
        for (int nt = 0; nt < 8; nt++) {
            float v0 = yacc[nt][h * 2], v1 = yacc[nt][h * 2 + 1];
            s += v0 + v1;
            sq += v0 * v0 + v1 * v1;
        }
        s  += __shfl_xor_sync(0xffffffffu, s, 1);
        s  += __shfl_xor_sync(0xffffffffu, s, 2);
        sq += __shfl_xor_sync(0xffffffffu, sq, 1);
        sq += __shfl_xor_sync(0xffffffffu, sq, 2);
        float mean = s * (1.0f / 64.0f);
        float var = sq * (1.0f / 64.0f) - mean * mean;
        float rstd = rsqrtf(var + 1e-5f);
        size_t fbase = ((size_t)bn * S_LEN + qi) * NDIM + g * 64;
#pragma unroll
        for (int nt = 0; nt < 8; nt++) {
            int col = nt * 8 + tig * 2;
            float w0 = gnw[g * 64 + col], w1 = gnw[g * 64 + col + 1];
            float b0 = gnb[g * 64 + col], b1 = gnb[g * 64 + col + 1];
            float2 gt = *(const float2*)&g_Gate[fbase + col];
            float o0 = ((yacc[nt][h * 2]     - mean) * rstd * w0 + b0) * gt.x;
            float o1 = ((yacc[nt][h * 2 + 1] - mean) * rstd * w1 + b1) * gt.y;
            g_AGh[(fbase + col) >> 1] = packh2(o0, o1);
        }
    }
}

// =================================================================
extern "C" void kernel_launch(void* const* d_in, const int* in_sizes, int n_in,
                              void* d_out, int out_size)
{
    const float* X   = (const float*)d_in[0];
    const float* WQ  = (const float*)d_in[1];
    const float* WK  = (const float*)d_in[2];
    const float* WV  = (const float*)d_in[3];
    const float* WG  = (const float*)d_in[4];
    const float* WO  = (const float*)d_in[5];
    const float* gnw = (const float*)d_in[6];
    const float* gnb = (const float*)d_in[7];
    float* out = (float*)d_out;

    cudaFuncSetAttribute((const void*)gemm_h<0, 128>,
                         cudaFuncAttributeMaxDynamicSharedMemorySize, GEMM_SMEM0);
    cudaFuncSetAttribute((const void*)gemm_h<2, 64>,
                         cudaFuncAttributeMaxDynamicSharedMemorySize, GEMM_SMEM2);
    cudaFuncSetAttribute((const void*)attn_h,
                         cudaFuncAttributeMaxDynamicSharedMemorySize, ATTN_SMEM);

    int prep_elems = M_TOT * KW + 5 * (WSZ / 2) + S_LEN * 32;
    prep_k<<<(prep_elems + 255) / 256, 256>>>(X, WQ, WK, WV, WG, WO);

    gemm_h<0, 128><<<dim3(NDIM / 128, M_TOT / 128, 4), 256, GEMM_SMEM0>>>(nullptr);
    attn_h<<<dim3(8, GBN), 256, ATTN_SMEM>>>(gnw, gnb);
    gemm_h<2, 64><<<dim3(NDIM / 64, M_TOT / 128, 1), 256, GEMM_SMEM2>>>(out);
}